// round 6
// baseline (speedup 1.0000x reference)
#include <cuda_runtime.h>
#include <cuda_bf16.h>
#include <cstdint>

// Problem constants (match reference)
#define BATCH      4
#define SEQ_LEN    8192
#define EMBED_DIM  512
#define NBUCKETS   500000
#define HASH_MASK  0x7FFFFFu   // 2^23 - 1
#define HASH_BASE  260u        // VOCAB + 1
#define MAX_N      8

// Gather load with L2 evict-last bias via cache-hint policy (the bare
// .L2::evict_last modifier is illegal on 16B loads on sm_103; the
// createpolicy + L2::cache_hint form is the sanctioned encoding).
__device__ __forceinline__ float4 ldg_evict_last(const float4* p, uint64_t pol)
{
    float4 v;
    asm("ld.global.nc.L2::cache_hint.v4.f32 {%0,%1,%2,%3}, [%4], %5;"
        : "=f"(v.x), "=f"(v.y), "=f"(v.z), "=f"(v.w)
        : "l"(p), "l"(pol));
    return v;
}

// One CTA per (b, s) position. 128 threads, each owns one float4 (4 floats)
// of the 512-dim embedding. Single kernel — size_w rows are L1/L2 resident,
// re-summed per thread (6 cached LDG.128, free under 25% issue).
__global__ __launch_bounds__(128, 10)
void hash_ngram_kernel(const int* __restrict__ tokens,
                       const float* __restrict__ main_w,
                       const float* __restrict__ shared_w,
                       const float* __restrict__ size_w,
                       float* __restrict__ out)
{
    const int pos = blockIdx.x;           // 0 .. BATCH*SEQ_LEN-1
    const int b   = pos >> 13;            // / SEQ_LEN
    const int s   = pos & (SEQ_LEN - 1);  // % SEQ_LEN

    __shared__ int tok[MAX_N];            // t[s], t[s-1], ..., t[s-7]

    if (threadIdx.x < MAX_N) {
        const int j = threadIdx.x;
        tok[j] = (s - j >= 0) ? tokens[b * SEQ_LEN + (s - j)] : 0;
    }
    __syncthreads();

    // Every thread computes the 6 bucket indices redundantly (pure ALU,
    // ~30 int ops) — avoids a second barrier / single-thread serialization.
    int sidx[MAX_N - 2];
    {
        unsigned P   = 1u;   // 260^j mod 2^23
        unsigned acc = 0u;   // running sum of masked terms
        #pragma unroll
        for (int j = 0; j < MAX_N; ++j) {
            acc += ((unsigned)tok[j] * P) & HASH_MASK;   // t[s-j]*260^j mod 2^23
            P = (P * HASH_BASE) & HASH_MASK;
            const int n = j + 1;                          // n-gram length
            if (n >= 3) {
                const unsigned h = acc & HASH_MASK;       // sum mod 2^23
                sidx[n - 3] = (s >= n - 1) ? (int)(h % NBUCKETS) : 0;
            }
        }
    }

    const int d4 = threadIdx.x;  // float4 lane, 0..127 (512/4)
    const float4* __restrict__ g4 = (const float4*)shared_w;
    const float4* __restrict__ m4 = (const float4*)main_w;
    const float4* __restrict__ z4 = (const float4*)size_w;

    // Build the evict-last policy once.
    uint64_t pol;
    asm("createpolicy.fractional.L2::evict_last.b64 %0, 1.0;" : "=l"(pol));

    // Issue the 6 DRAM gathers first for maximum MLP.
    float4 vg[MAX_N - 2];
    #pragma unroll
    for (int r = 0; r < MAX_N - 2; ++r)
        vg[r] = ldg_evict_last(&g4[(size_t)sidx[r] * 128 + d4], pol);

    // While gathers are in flight: accumulate the cached contributions
    // (main_w row is L2-resident; size_w is L1-resident).
    float4 vm = __ldg(&m4[(size_t)tok[0] * 128 + d4]);
    float ax = vm.x, ay = vm.y, az = vm.z, aw = vm.w;
    #pragma unroll
    for (int r = 0; r < MAX_N - 2; ++r) {
        float4 vz = __ldg(&z4[(size_t)r * 128 + d4]);
        ax += vz.x; ay += vz.y; az += vz.z; aw += vz.w;
    }

    // Consume the gathers.
    #pragma unroll
    for (int r = 0; r < MAX_N - 2; ++r) {
        ax += vg[r].x;
        ay += vg[r].y;
        az += vg[r].z;
        aw += vg[r].w;
    }

    const float inv = 1.0f / 7.0f;   // 1 + (MAX_N - 2) contributors
    float4 o;
    o.x = ax * inv; o.y = ay * inv; o.z = az * inv; o.w = aw * inv;
    // Streaming store: don't let the 64MB output evict gather lines from L2.
    __stcs(&((float4*)out)[(size_t)pos * 128 + d4], o);
}

extern "C" void kernel_launch(void* const* d_in, const int* in_sizes, int n_in,
                              void* d_out, int out_size)
{
    const int*   tokens   = (const int*)  d_in[0];   // [4, 8192] int32
    const float* main_w   = (const float*)d_in[1];   // [259, 512] f32
    const float* shared_w = (const float*)d_in[2];   // [500000, 512] f32
    const float* size_w   = (const float*)d_in[3];   // [6, 512] f32
    float*       out      = (float*)d_out;           // [4, 8192, 512] f32

    (void)in_sizes; (void)n_in; (void)out_size;

    hash_ngram_kernel<<<BATCH * SEQ_LEN, 128>>>(tokens, main_w, shared_w, size_w, out);
}